// round 16
// baseline (speedup 1.0000x reference)
#include <cuda_runtime.h>
#include <cstdint>

// ================= problem constants =================
#define BB 16
#define CC 256
#define NT 288                       // 9 warps = 9 q-displacements
#define SROW1 264                    // x1 smem row stride (floats), ≡8 mod 32
#define X1ROWS 24                    // 1 i-row x 24 j
#define SMEM_BYTES 28800             // max(tile 24*264*4=25344, epi 9*800*4=28800)

// A: K-major, channel pair-permuted within 8: g_At[b][i*24+j][k']
__device__ __align__(16) float g_At[(size_t)BB * 576 * CC];
// B: fragment-major [b][y'(32)][kc(32)][mt(2)][lane(32)][4]; .bss zeros = padding
__device__ __align__(16) float g_B2[(size_t)BB * 32 * 32 * 2 * 128];

__device__ __forceinline__ float tf32r(float x) {
    uint32_t u;
    asm("cvt.rna.tf32.f32 %0, %1;" : "=r"(u) : "f"(x));
    return __uint_as_float(u);
}
__device__ __forceinline__ uint32_t smem_u32(const void* p) {
    uint32_t a;
    asm("{ .reg .u64 t; cvta.to.shared.u64 t, %1; cvt.u32.u64 %0, t; }"
        : "=r"(a) : "l"(p));
    return a;
}
__device__ __forceinline__ void cp16(uint32_t s, const float* g) {
    asm volatile("cp.async.cg.shared.global [%0], [%1], 16;" :: "r"(s), "l"(g));
}
__device__ __forceinline__ void mma_tf32(float* d, const uint32_t* a,
                                         const uint32_t* b) {
    asm volatile(
        "mma.sync.aligned.m16n8k8.row.col.f32.tf32.tf32.f32 "
        "{%0,%1,%2,%3}, {%4,%5,%6,%7}, {%8,%9}, {%0,%1,%2,%3};"
        : "+f"(d[0]), "+f"(d[1]), "+f"(d[2]), "+f"(d[3])
        : "r"(a[0]), "r"(a[1]), "r"(a[2]), "r"(a[3]), "r"(b[0]), "r"(b[1]));
}

// ===== prep: single-barrier; A->pair-permuted K-major, B->fragment-major =====
__global__ __launch_bounds__(256, 4)
void prep_kernel(const float* __restrict__ x1, const float* __restrict__ x2)
{
    __shared__ float tile[256][25];      // all channels x 24 even-cols (+1 pad)
    const int row = blockIdx.x;          // 0..23 : i (A) or y (B)
    const int b   = blockIdx.y >> 1;
    const bool isB = blockIdx.y & 1;
    const float* src = isB ? x2 : x1;
    const int t = threadIdx.x;

    // load: thread t owns channel t; 12 LDG.128, keep even lanes, tf32-round
    {
        const float4* srow = (const float4*)
            (src + ((size_t)(b * CC + t) * 48 + 2 * row) * 48);
        #pragma unroll
        for (int m = 0; m < 12; ++m) {
            float4 v = srow[m];
            tile[t][2 * m]     = tf32r(v.x);
            tile[t][2 * m + 1] = tf32r(v.z);
        }
    }
    __syncthreads();                     // the only barrier

    if (!isB) {
        // inverse pair-permutation: dest k' = t reads source channel c_src
        const int k8 = t & 7;
        const int c8 = (k8 & 1) ? 4 + (k8 >> 1) : (k8 >> 1);
        const int c_src = (t & ~7) | c8;
        float* dst = g_At + (size_t)(b * 576 + row * 24) * CC + t;
        #pragma unroll
        for (int jj = 0; jj < 24; ++jj)
            dst[jj * CC] = tile[c_src][jj];   // 1KB coalesced per jj
    } else {
        // per-thread constants (lin & 255 == t for all e)
        const int mt   = t >> 7;
        const int rem2 = t & 127;
        const int lane = rem2 >> 2, el = rem2 & 3;
        const int g = lane >> 2, t4 = lane & 3;
        const int xp = mt * 16 + g + 8 * (el & 1);       // x' 0..31
        const int c0 = t4 + 4 * (el >> 1);               // k base within 8
        const bool val = (xp >= 4 && xp < 28);
        const int xs = val ? (xp - 4) : 0;
        float* dst = g_B2 + ((size_t)(b * 32 + row + 4) * 32) * 256
                     + mt * 128 + rem2;
        #pragma unroll
        for (int e = 0; e < 32; ++e) {                    // (cb,kcl) = (e>>2, e&3)
            float v = val ? tile[c0 + 8 * e][xs] : 0.f;
            dst[e * 256] = v;                             // coalesced 512B segments
        }
    }
}

// ===== barrier-free banded TF32 warp-MMA; 1 i-row per CTA, 3 CTAs/SM =====
__global__ __launch_bounds__(NT, 3)
void mma_kernel(float* __restrict__ out)
{
    extern __shared__ float sm[];
    const uint32_t smb = smem_u32(sm);
    const int tid = threadIdx.x;
    const int q = tid >> 5, lane = tid & 31;
    const int g = lane >> 2, t4 = lane & 3;
    const int i0 = blockIdx.x;           // 0..23
    const int b  = blockIdx.y;

    // ---- one-shot x1 tile load: 24 rows x 256 k' (pair-permuted) ----
    {
        const float* Ab = g_At + (size_t)(b * 576 + i0 * 24) * CC;
        for (int e = tid; e < X1ROWS * 64; e += NT) {
            int r = e >> 6, s = e & 63;
            cp16(smb + (uint32_t)(r * (SROW1 * 4) + s * 16), Ab + r * CC + s * 4);
        }
        asm volatile("cp.async.commit_group;" ::: "memory");
        asm volatile("cp.async.wait_group 0;" ::: "memory");
    }
    __syncthreads();                     // the ONLY block barrier before epilogue

    // x2 fragments: one LDG.128 per (kc, mt)
    const float4* __restrict__ Bq = (const float4*)
        (g_B2 + (size_t)(b * 32 + i0 + q) * 8192) + lane;

    float acc[2][3][4];
    #pragma unroll
    for (int mt = 0; mt < 2; ++mt)
        #pragma unroll
        for (int nt = 0; nt < 3; ++nt)
            #pragma unroll
            for (int e = 0; e < 4; ++e) acc[mt][nt][e] = 0.f;

    #pragma unroll 4
    for (int kc = 0; kc < 32; ++kc) {
        uint32_t af[2][4], bf[3][2];
        #pragma unroll
        for (int mt = 0; mt < 2; ++mt) {
            float4 v = Bq[kc * 64 + mt * 32];
            af[mt][0] = __float_as_uint(v.x);
            af[mt][1] = __float_as_uint(v.y);
            af[mt][2] = __float_as_uint(v.z);
            af[mt][3] = __float_as_uint(v.w);
        }
        #pragma unroll
        for (int nt = 0; nt < 3; ++nt) {
            float2 bp = *(const float2*)(sm + (nt * 8 + g) * SROW1 + kc * 8 + 2 * t4);
            bf[nt][0] = __float_as_uint(bp.x);
            bf[nt][1] = __float_as_uint(bp.y);
        }
        #pragma unroll
        for (int mt = 0; mt < 2; ++mt)
            #pragma unroll
            for (int nt = 0; nt < 3; ++nt)
                mma_tf32(acc[mt][nt], af[mt], bf[nt]);
    }
    __syncthreads();                     // warps done with x1s; reuse as scratch

    // epilogue: warp q scratch 32x25
    float* S = sm + q * 800;
    const float sc = 1.0f / 256.0f;
    #pragma unroll
    for (int mt = 0; mt < 2; ++mt)
        #pragma unroll
        for (int nt = 0; nt < 3; ++nt) {
            float* s0 = S + (mt * 16 + g) * 25 + nt * 8 + 2 * t4;
            s0[0]          = acc[mt][nt][0];
            s0[1]          = acc[mt][nt][1];
            s0[8 * 25]     = acc[mt][nt][2];
            s0[8 * 25 + 1] = acc[mt][nt][3];
        }
    __syncwarp();
    float* ob = out + ((size_t)b * 81 + q * 9) * 576 + i0 * 24;
    if (lane < 24) {
        #pragma unroll
        for (int p = 0; p < 9; ++p)
            ob[p * 576 + lane] = S[(lane + p) * 25 + lane] * sc;
    }
}

extern "C" void kernel_launch(void* const* d_in, const int* in_sizes, int n_in,
                              void* d_out, int out_size)
{
    const float* x1 = (const float*)d_in[0];
    const float* x2 = (const float*)d_in[1];
    float* out = (float*)d_out;

    cudaFuncSetAttribute(mma_kernel,
                         cudaFuncAttributeMaxDynamicSharedMemorySize, SMEM_BYTES);

    dim3 pgrid(24, 32);
    prep_kernel<<<pgrid, 256>>>(x1, x2);              // launch 0
    dim3 mgrid(24, BB);
    mma_kernel<<<mgrid, NT, SMEM_BYTES>>>(out);       // launch 1 -> idx 3 profiled
}

// round 17
// speedup vs baseline: 1.6268x; 1.6268x over previous
#include <cuda_runtime.h>
#include <cstdint>

// ================= problem constants =================
#define BB 16
#define CC 256
#define NT 288                       // 9 warps = 9 q-displacements
#define SROW1 272                    // x1 smem row stride (floats) ≡16 mod 32
#define X1ROWS 24                    // 1 i-row x 24 j
#define SMEM_BYTES 28800             // max(tile 24*272*4=26112, epi 9*800*4=28800)

// A: K-major, 16-wide channel-permuted: pos p=4*t4+d holds k=t4+4d (within 16)
__device__ __align__(16) float g_At[(size_t)BB * 576 * CC];
// B: fragment-major [b][y'(32)][kc(32)][mt(2)][lane(32)][4]; .bss zeros = padding
__device__ __align__(16) float g_B2[(size_t)BB * 32 * 32 * 2 * 128];

__device__ __forceinline__ float tf32r(float x) {
    uint32_t u;
    asm("cvt.rna.tf32.f32 %0, %1;" : "=r"(u) : "f"(x));
    return __uint_as_float(u);
}
__device__ __forceinline__ uint32_t smem_u32(const void* p) {
    uint32_t a;
    asm("{ .reg .u64 t; cvta.to.shared.u64 t, %1; cvt.u32.u64 %0, t; }"
        : "=r"(a) : "l"(p));
    return a;
}
__device__ __forceinline__ void cp16(uint32_t s, const float* g) {
    asm volatile("cp.async.cg.shared.global [%0], [%1], 16;" :: "r"(s), "l"(g));
}
__device__ __forceinline__ void mma_tf32(float* d, const uint32_t* a,
                                         const uint32_t* b) {
    asm volatile(
        "mma.sync.aligned.m16n8k8.row.col.f32.tf32.tf32.f32 "
        "{%0,%1,%2,%3}, {%4,%5,%6,%7}, {%8,%9}, {%0,%1,%2,%3};"
        : "+f"(d[0]), "+f"(d[1]), "+f"(d[2]), "+f"(d[3])
        : "r"(a[0]), "r"(a[1]), "r"(a[2]), "r"(a[3]), "r"(b[0]), "r"(b[1]));
}

// ===== prep (round-15 structure): A->16-permuted K-major, B->fragment-major =====
__global__ void prep_kernel(const float* __restrict__ x1,
                            const float* __restrict__ x2)
{
    __shared__ float tile[32][25];
    const int row = blockIdx.x;          // 0..23 : i (A) or y (B)
    const int b   = blockIdx.y >> 1;
    const bool isB = blockIdx.y & 1;
    const float* src = isB ? x2 : x1;
    const int t = threadIdx.x;

    #pragma unroll 1
    for (int cb = 0; cb < 8; ++cb) {
        const int c0 = cb * 32;
        {
            const int c  = t >> 3;
            const int j0 = (t & 7) * 3;
            const float* srow = src + ((size_t)(b * CC + c0 + c) * 48 + 2 * row) * 48;
            #pragma unroll
            for (int e = 0; e < 3; ++e)
                tile[c][j0 + e] = tf32r(srow[2 * (j0 + e)]);
        }
        __syncthreads();
        if (!isB) {
            // forward 16-wide permutation: channel c -> position cp
            const int c = t & 31, jb = t >> 5;
            const int c16 = c & 15;
            const int cp = (c & ~15) | (4 * (c16 & 3) + (c16 >> 2));
            #pragma unroll
            for (int e = 0; e < 3; ++e) {
                int j = jb + 8 * e;
                g_At[((size_t)(b * 576 + row * 24 + j)) * CC + c0 + cp] = tile[c][j];
            }
        } else {
            // 1024 floats: [kcl(4)][mt(2)][lane(32)][el(4)]
            #pragma unroll
            for (int e = 0; e < 4; ++e) {
                int lin = t + 256 * e;           // 0..1023
                int kcl  = lin >> 8;
                int rem  = lin & 255;
                int mt   = rem >> 7;
                int rem2 = rem & 127;
                int lane = rem2 >> 2, el = rem2 & 3;
                int gg = lane >> 2, tt4 = lane & 3;
                int xp = mt * 16 + gg + 8 * (el & 1);      // x' 0..31
                int c  = kcl * 8 + tt4 + 4 * (el >> 1);    // k within 32
                float v = (xp >= 4 && xp < 28) ? tile[c][xp - 4] : 0.f;
                size_t idx = (((size_t)(b * 32 + row + 4) * 32 + cb * 4 + kcl) * 2 + mt)
                             * 128 + rem2;
                g_B2[idx] = v;
            }
        }
        __syncthreads();
    }
}

// ===== barrier-free banded TF32 warp-MMA; 1 i-row per CTA, 3 CTAs/SM =====
__global__ __launch_bounds__(NT, 3)
void mma_kernel(float* __restrict__ out)
{
    extern __shared__ float sm[];
    const uint32_t smb = smem_u32(sm);
    const int tid = threadIdx.x;
    const int q = tid >> 5, lane = tid & 31;
    const int g = lane >> 2, t4 = lane & 3;
    const int i0 = blockIdx.x;           // 0..23
    const int b  = blockIdx.y;

    // ---- one-shot x1 tile load: 24 rows x 256 k' (16-permuted) ----
    {
        const float* Ab = g_At + (size_t)(b * 576 + i0 * 24) * CC;
        for (int e = tid; e < X1ROWS * 64; e += NT) {
            int r = e >> 6, s = e & 63;
            cp16(smb + (uint32_t)(r * (SROW1 * 4) + s * 16), Ab + r * CC + s * 4);
        }
        asm volatile("cp.async.commit_group;" ::: "memory");
        asm volatile("cp.async.wait_group 0;" ::: "memory");
    }
    __syncthreads();                     // the ONLY block barrier before epilogue

    // x2 fragments: one LDG.128 per (kc, mt)
    const float4* __restrict__ Bq = (const float4*)
        (g_B2 + (size_t)(b * 32 + i0 + q) * 8192) + lane;

    float acc[2][3][4];
    #pragma unroll
    for (int mt = 0; mt < 2; ++mt)
        #pragma unroll
        for (int nt = 0; nt < 3; ++nt)
            #pragma unroll
            for (int e = 0; e < 4; ++e) acc[mt][nt][e] = 0.f;

    #pragma unroll 4
    for (int kcp = 0; kcp < 16; ++kcp) {   // kc pair (2*kcp, 2*kcp+1)
        uint32_t af0[2][4], af1[2][4], bf0[3][2], bf1[3][2];
        #pragma unroll
        for (int mt = 0; mt < 2; ++mt) {
            float4 v0 = Bq[(2 * kcp) * 64 + mt * 32];
            float4 v1 = Bq[(2 * kcp + 1) * 64 + mt * 32];
            af0[mt][0] = __float_as_uint(v0.x); af0[mt][1] = __float_as_uint(v0.y);
            af0[mt][2] = __float_as_uint(v0.z); af0[mt][3] = __float_as_uint(v0.w);
            af1[mt][0] = __float_as_uint(v1.x); af1[mt][1] = __float_as_uint(v1.y);
            af1[mt][2] = __float_as_uint(v1.z); af1[mt][3] = __float_as_uint(v1.w);
        }
        #pragma unroll
        for (int nt = 0; nt < 3; ++nt) {
            // one LDS.128 per (nt, kc-pair): pos 4*t4+d holds k=t4+4d within 16
            float4 w = *(const float4*)(sm + (nt * 8 + g) * SROW1
                                        + kcp * 16 + 4 * t4);
            bf0[nt][0] = __float_as_uint(w.x);   // k = 16kcp + t4
            bf0[nt][1] = __float_as_uint(w.y);   // k = 16kcp + t4 + 4
            bf1[nt][0] = __float_as_uint(w.z);   // k = 16kcp + 8 + t4
            bf1[nt][1] = __float_as_uint(w.w);   // k = 16kcp + 8 + t4 + 4
        }
        #pragma unroll
        for (int mt = 0; mt < 2; ++mt)
            #pragma unroll
            for (int nt = 0; nt < 3; ++nt) {
                mma_tf32(acc[mt][nt], af0[mt], bf0[nt]);
                mma_tf32(acc[mt][nt], af1[mt], bf1[nt]);
            }
    }
    __syncthreads();                     // warps done with x1s; reuse as scratch

    // epilogue: warp q scratch 32x25
    float* S = sm + q * 800;
    const float sc = 1.0f / 256.0f;
    #pragma unroll
    for (int mt = 0; mt < 2; ++mt)
        #pragma unroll
        for (int nt = 0; nt < 3; ++nt) {
            float* s0 = S + (mt * 16 + g) * 25 + nt * 8 + 2 * t4;
            s0[0]          = acc[mt][nt][0];
            s0[1]          = acc[mt][nt][1];
            s0[8 * 25]     = acc[mt][nt][2];
            s0[8 * 25 + 1] = acc[mt][nt][3];
        }
    __syncwarp();
    float* ob = out + ((size_t)b * 81 + q * 9) * 576 + i0 * 24;
    if (lane < 24) {
        #pragma unroll
        for (int p = 0; p < 9; ++p)
            ob[p * 576 + lane] = S[(lane + p) * 25 + lane] * sc;
    }
}

extern "C" void kernel_launch(void* const* d_in, const int* in_sizes, int n_in,
                              void* d_out, int out_size)
{
    const float* x1 = (const float*)d_in[0];
    const float* x2 = (const float*)d_in[1];
    float* out = (float*)d_out;

    cudaFuncSetAttribute(mma_kernel,
                         cudaFuncAttributeMaxDynamicSharedMemorySize, SMEM_BYTES);

    dim3 pgrid(24, 32);
    prep_kernel<<<pgrid, 256>>>(x1, x2);              // launch 0
    dim3 mgrid(24, BB);
    mma_kernel<<<mgrid, NT, SMEM_BYTES>>>(out);       // launch 1 -> idx 3 profiled
}